// round 1
// baseline (speedup 1.0000x reference)
#include <cuda_runtime.h>
#include <cuda_bf16.h>

#define D 128
#define NMAX 50000

// ---------------- device scratch (no allocation allowed) ----------------
__device__ float g_aggr[NMAX * D];   // per-layer mean-aggregation accumulator
__device__ float g_buf[NMAX * D];    // ping-pong activation buffer
__device__ float g_deg[NMAX];        // degree -> inv_deg
__device__ int   g_is64;             // 1 if edge_index is int64, 0 if int32

// ---------------- helpers ----------------
__device__ __forceinline__ int load_edge_idx(const void* base, long long i) {
    if (g_is64) return (int)((const long long*)base)[i];
    return ((const int*)base)[i];
}

__device__ __forceinline__ void red_add_v4(float* ptr, float4 v) {
    asm volatile("red.global.add.v4.f32 [%0], {%1,%2,%3,%4};"
                 :: "l"(ptr), "f"(v.x), "f"(v.y), "f"(v.z), "f"(v.w)
                 : "memory");
}

// ---------------- dtype detection ----------------
// If edge_index is truly int64 with values in [0, 50000), every odd 32-bit
// word (high half) is zero. If it is int32, odd words are src[1],src[3],...
// (random in [0,50000)) — some will be nonzero.
__global__ void k_detect(const int* ei32, int E) {
    if (blockIdx.x == 0 && threadIdx.x == 0) {
        int is64 = 1;
        int lim = E < 512 ? E : 512;
        for (int i = 0; i < lim; i++) {
            if (ei32[2 * i + 1] != 0) { is64 = 0; break; }
        }
        g_is64 = is64;
    }
}

// ---------------- degree ----------------
__global__ void k_zero_deg(int n) {
    int i = blockIdx.x * blockDim.x + threadIdx.x;
    if (i < n) g_deg[i] = 0.0f;
}

__global__ void k_count(const void* ei, int E) {
    int i = blockIdx.x * blockDim.x + threadIdx.x;
    if (i >= E) return;
    int d = load_edge_idx(ei, (long long)E + i);  // dst row
    atomicAdd(&g_deg[d], 1.0f);
}

__global__ void k_finalize_deg(int n) {
    int i = blockIdx.x * blockDim.x + threadIdx.x;
    if (i < n) g_deg[i] = 1.0f / fmaxf(g_deg[i], 1.0f);
}

// ---------------- zero aggr ----------------
__global__ void k_zero_aggr(int total4) {
    int i = blockIdx.x * blockDim.x + threadIdx.x;
    if (i < total4) ((float4*)g_aggr)[i] = make_float4(0.f, 0.f, 0.f, 0.f);
}

// ---------------- scatter-add (segment_sum of messages) ----------------
// One edge handled by 32 consecutive threads; each thread moves one float4.
__global__ void k_scatter(const float* __restrict__ x, const void* __restrict__ ei, int E) {
    int idx = blockIdx.x * blockDim.x + threadIdx.x;
    if (idx >= E * 32) return;
    int e = idx >> 5;
    int c = (idx & 31) << 2;
    int s = load_edge_idx(ei, e);                  // src row
    int d = load_edge_idx(ei, (long long)E + e);   // dst row
    float4 v = *(const float4*)(x + (long long)s * D + c);
    red_add_v4(&g_aggr[(long long)d * D + c], v);
}

// ---------------- fused SAGE layer GEMM ----------------
// out[r, :] = (inv_deg[r] * aggr[r, :]) @ Wl + b + x[r, :] @ Wr   (+ ReLU)
// Block: 256 threads, tile = 32 rows x 128 cols, both W matrices in smem.
#define TPAD 36   // padded row stride (floats) for transposed tiles: 36*4B = 144B (16B aligned)

__global__ __launch_bounds__(256, 1)
void k_sage(const float* __restrict__ x_in,
            const float* __restrict__ Wl, const float* __restrict__ Wr,
            const float* __restrict__ bias,
            float* __restrict__ out, int n, int do_relu) {
    extern __shared__ float sm[];
    float* Wl_s = sm;                 // [128][128]
    float* Wr_s = sm + D * D;         // [128][128]
    float* aT   = sm + 2 * D * D;     // [128][TPAD] (k-major, rows contiguous)
    float* xT   = aT + D * TPAD;      // [128][TPAD]

    int tid = threadIdx.x;

    // Load both weight matrices (row-major, K rows x 128 cols)
    const float4* Wl4 = (const float4*)Wl;
    const float4* Wr4 = (const float4*)Wr;
    float4* Wl_s4 = (float4*)Wl_s;
    float4* Wr_s4 = (float4*)Wr_s;
    #pragma unroll 4
    for (int i = tid; i < D * D / 4; i += 256) {
        Wl_s4[i] = Wl4[i];
        Wr_s4[i] = Wr4[i];
    }

    int row0 = blockIdx.x * 32;

    // Load transposed 32-row activation tiles. Warp layout: r = t&31 varies
    // within a warp -> STS addresses are consecutive -> conflict-free.
    for (int t = tid; t < 1024; t += 256) {
        int r  = t & 31;
        int c4 = t >> 5;           // 0..31, k = c4*4
        int row = row0 + r;
        float4 av = make_float4(0.f, 0.f, 0.f, 0.f);
        float4 xv = make_float4(0.f, 0.f, 0.f, 0.f);
        if (row < n) {
            float s = g_deg[row];  // inv_deg
            av = *(const float4*)(g_aggr + (long long)row * D + c4 * 4);
            av.x *= s; av.y *= s; av.z *= s; av.w *= s;
            xv = *(const float4*)(x_in + (long long)row * D + c4 * 4);
        }
        int k = c4 * 4;
        aT[(k + 0) * TPAD + r] = av.x;
        aT[(k + 1) * TPAD + r] = av.y;
        aT[(k + 2) * TPAD + r] = av.z;
        aT[(k + 3) * TPAD + r] = av.w;
        xT[(k + 0) * TPAD + r] = xv.x;
        xT[(k + 1) * TPAD + r] = xv.y;
        xT[(k + 2) * TPAD + r] = xv.z;
        xT[(k + 3) * TPAD + r] = xv.w;
    }
    __syncthreads();

    int tx = tid & 31;  // column group (4 cols each -> 128 cols)
    int ty = tid >> 5;  // row group    (4 rows each -> 32 rows)

    float acc[4][4];
    #pragma unroll
    for (int i = 0; i < 4; i++)
        #pragma unroll
        for (int j = 0; j < 4; j++) acc[i][j] = 0.f;

    #pragma unroll 4
    for (int k = 0; k < D; k++) {
        float4 a  = *(const float4*)(aT + k * TPAD + ty * 4);   // broadcast within warp
        float4 xv = *(const float4*)(xT + k * TPAD + ty * 4);   // broadcast
        float4 wl = *(const float4*)(Wl_s + k * D + tx * 4);    // conflict-free
        float4 wr = *(const float4*)(Wr_s + k * D + tx * 4);    // conflict-free
        float ar[4] = {a.x, a.y, a.z, a.w};
        float xr[4] = {xv.x, xv.y, xv.z, xv.w};
        float wlr[4] = {wl.x, wl.y, wl.z, wl.w};
        float wrr[4] = {wr.x, wr.y, wr.z, wr.w};
        #pragma unroll
        for (int i = 0; i < 4; i++)
            #pragma unroll
            for (int j = 0; j < 4; j++)
                acc[i][j] += ar[i] * wlr[j] + xr[i] * wrr[j];
    }

    float4 bv = *(const float4*)(bias + tx * 4);
    float br[4] = {bv.x, bv.y, bv.z, bv.w};
    #pragma unroll
    for (int i = 0; i < 4; i++) {
        int row = row0 + ty * 4 + i;
        if (row < n) {
            float o[4];
            #pragma unroll
            for (int j = 0; j < 4; j++) {
                o[j] = acc[i][j] + br[j];
                if (do_relu) o[j] = fmaxf(o[j], 0.f);
            }
            *(float4*)(out + (long long)row * D + tx * 4) =
                make_float4(o[0], o[1], o[2], o[3]);
        }
    }
}

// ---------------- host launcher ----------------
extern "C" void kernel_launch(void* const* d_in, const int* in_sizes, int n_in,
                              void* d_out, int out_size) {
    const float* x  = (const float*)d_in[0];
    const void*  ei = d_in[1];
    const float* Wl = (const float*)d_in[2];
    const float* bl = (const float*)d_in[3];
    const float* Wr = (const float*)d_in[4];
    float* out = (float*)d_out;

    int n = in_sizes[0] / D;
    int E = in_sizes[1] / 2;
    int L = in_sizes[2] / (D * D);

    void* pbuf = nullptr;
    cudaGetSymbolAddress(&pbuf, g_buf);
    float* buf = (float*)pbuf;

    int smem_bytes = (2 * D * D + 2 * D * TPAD) * (int)sizeof(float);
    cudaFuncSetAttribute(k_sage, cudaFuncAttributeMaxDynamicSharedMemorySize, smem_bytes);

    // dtype detection (int64 vs int32 edge_index)
    k_detect<<<1, 32>>>((const int*)ei, E);

    // degree -> inv_deg
    k_zero_deg<<<(n + 255) / 256, 256>>>(n);
    k_count<<<(E + 255) / 256, 256>>>(ei, E);
    k_finalize_deg<<<(n + 255) / 256, 256>>>(n);

    const float* cur = x;
    for (int l = 0; l < L; l++) {
        int t4 = n * D / 4;
        k_zero_aggr<<<(t4 + 255) / 256, 256>>>(t4);
        int tot = E * 32;
        k_scatter<<<(tot + 255) / 256, 256>>>(cur, ei, E);
        float* o = (l % 2 == 0) ? out : buf;  // L-1 even -> last layer lands in out
        k_sage<<<(n + 31) / 32, 256, smem_bytes>>>(
            cur, Wl + (long long)l * D * D, Wr + (long long)l * D * D,
            bl + (long long)l * D, o, n, l < L - 1 ? 1 : 0);
        cur = o;
    }
    if (cur != out) {
        cudaMemcpyAsync(out, cur, (size_t)n * D * sizeof(float),
                        cudaMemcpyDeviceToDevice);
    }
}